// round 15
// baseline (speedup 1.0000x reference)
#include <cuda_runtime.h>
#include <math.h>

#define EPSV 1e-20f

#define BB 16
#define H0 352
#define W0 1216
#define H1 176
#define W1 608
#define H2 88
#define W2 304
#define H3 44
#define W3 152

#define P0 (H0*W0)
#define P1 (H1*W1)
#define P2 (H2*W2)
#define P3 (H3*W3)

#define M0 ((size_t)BB*2*P0)
#define M1 ((size_t)BB*2*P1)
#define M2 ((size_t)BB*2*P2)
#define M3 ((size_t)BB*2*P3)

typedef unsigned long long ull;

__device__ __align__(16) float2 g_scratch[3*M0 + 3*M1 + 3*M2 + 2*M3];
__device__ ull   g_wd[480];
__device__ float g_ws[32];

// dup-pair weight layout (ull): w1:0(50) w2:50(100) w3:150(100) w4:250(72)
// w5:322(72) w6:394(72) w7:466(4); entry OFF+(ci*K+k)*2+cout
// g_ws: sums [2*lyr+co], biases [16+2*lyr+co]

__device__ __forceinline__ ull fma2(ull a, ull b, ull c){
    ull d; asm("fma.rn.f32x2 %0, %1, %2, %3;" : "=l"(d) : "l"(a), "l"(b), "l"(c)); return d;
}
__device__ __forceinline__ void unpack2(ull v, float &a, float &b){
    asm("mov.b64 {%0,%1}, %2;" : "=f"(a), "=f"(b) : "l"(v));
}
__device__ __forceinline__ ull dupf(float w){
    float2 f2 = make_float2(w, w);
    return *(ull*)&f2;
}
__device__ __forceinline__ float sp10(float p){
    float z = 10.0f * p;
    float r = (z > 20.0f) ? z : log1pf(expf(z));
    return r * 0.1f;
}

__global__ void k_prep(const float* __restrict__ w1, const float* __restrict__ b1,
                       const float* __restrict__ w2, const float* __restrict__ b2,
                       const float* __restrict__ w3, const float* __restrict__ b3,
                       const float* __restrict__ w4, const float* __restrict__ b4,
                       const float* __restrict__ w5, const float* __restrict__ b5,
                       const float* __restrict__ w6, const float* __restrict__ b6,
                       const float* __restrict__ w7, const float* __restrict__ b7){
    const float* wp[7]={w1,w2,w3,w4,w5,w6,w7};
    const float* bp[7]={b1,b2,b3,b4,b5,b6,b7};
    const int cin[7]={1,2,2,4,4,4,2};
    const int kk [7]={25,25,25,9,9,9,1};
    const int co [7]={2,2,2,2,2,2,1};
    const int off[7]={0,50,150,250,322,394,466};
    int t=threadIdx.x;
    for(int l=0;l<7;l++){
        int n=cin[l]*kk[l];
        int tot=n*co[l];
        for(int i=t;i<tot;i+=blockDim.x){
            int c=i/n, e=i%n;
            g_wd[off[l]+e*2+c]=dupf(sp10(wp[l][c*n+e]));
        }
    }
    __syncthreads();
    if(t==0){
        for(int l=0;l<7;l++){
            int n=cin[l]*kk[l];
            for(int c=0;c<co[l];c++){
                float s=0.f;
                for(int e=0;e<n;e++){ float lo,hi; unpack2(g_wd[off[l]+e*2+c],lo,hi); s+=lo; }
                g_ws[2*l+c]=s;
                g_ws[16+2*l+c]=bp[l][c];
            }
        }
    }
}

// ---- generic 4x2 tile 5x5 conv accumulate from smem planes ----
template<int CIN>
__device__ __forceinline__ void tile5_acc(const float2* __restrict__ sp, int planeSz, int sw,
                                          const ull* __restrict__ w,
                                          int tx4, int ty2, ull acc[2][2][4]){
    #pragma unroll
    for(int a=0;a<2;a++)
      #pragma unroll
      for(int dy=0;dy<2;dy++)
        #pragma unroll
        for(int dx=0;dx<4;dx++) acc[a][dy][dx]=0ull;
    #pragma unroll
    for(int ci=0;ci<CIN;ci++){
        const float2* s = sp + ci*planeSz;
        ull v[2][8];
        {
            const longlong2* p = (const longlong2*)&s[ty2*sw + tx4];
            #pragma unroll
            for(int j=0;j<4;j++){ longlong2 q=p[j]; v[0][2*j]=(ull)q.x; v[0][2*j+1]=(ull)q.y; }
        }
        #pragma unroll
        for(int ky=0;ky<5;ky++){
            const int cur = ky & 1, nxt = (ky+1) & 1;
            {
                const longlong2* p = (const longlong2*)&s[(ty2+ky+1)*sw + tx4];
                #pragma unroll
                for(int j=0;j<4;j++){ longlong2 q=p[j]; v[nxt][2*j]=(ull)q.x; v[nxt][2*j+1]=(ull)q.y; }
            }
            #pragma unroll
            for(int kx=0;kx<5;kx++){
                longlong2 wp = *(const longlong2*)&w[(ci*25 + ky*5 + kx)*2];
                ull wa=(ull)wp.x, wb=(ull)wp.y;
                #pragma unroll
                for(int dx=0;dx<4;dx++){
                    acc[0][0][dx]=fma2(wa, v[cur][kx+dx], acc[0][0][dx]);
                    acc[1][0][dx]=fma2(wb, v[cur][kx+dx], acc[1][0][dx]);
                    acc[0][1][dx]=fma2(wa, v[nxt][kx+dx], acc[0][1][dx]);
                    acc[1][1][dx]=fma2(wb, v[nxt][kx+dx], acc[1][1][dx]);
                }
            }
        }
    }
}

// mid-stage epilogue: write (c, x*c) into smem planes, zero outside image
__device__ __forceinline__ void epi_mid(ull acc[2][2][4], float2* dst, int planeSz, int dw,
                                        int tx4, int ty2,
                                        float rs0, float rs1, float bi0, float bi1,
                                        int gx0, int gy0, int W, int H){
    #pragma unroll
    for(int a=0;a<2;a++){
        float rsa = a?rs1:rs0, bia = a?bi1:bi0;
        #pragma unroll
        for(int dy=0;dy<2;dy++){
            int gy = gy0 + ty2 + dy;
            bool rowok = (unsigned)gy < (unsigned)H;
            float2 o[4];
            #pragma unroll
            for(int j=0;j<2;j++){
                float d0,n0,d1,n1;
                unpack2(acc[a][dy][2*j],   d0, n0);
                unpack2(acc[a][dy][2*j+1], d1, n1);
                float x0 = n0/(d0+EPSV)+bia, c0 = d0*rsa;
                float x1 = n1/(d1+EPSV)+bia, c1 = d1*rsa;
                o[2*j]   = make_float2(c0, x0*c0);
                o[2*j+1] = make_float2(c1, x1*c1);
            }
            #pragma unroll
            for(int dx=0;dx<4;dx++){
                int gx = gx0 + tx4 + dx;
                if(!rowok || (unsigned)gx >= (unsigned)W) o[dx] = make_float2(0.f,0.f);
            }
            float4* p = (float4*)&dst[a*planeSz + (ty2+dy)*dw + tx4];
            p[0] = make_float4(o[0].x,o[0].y,o[1].x,o[1].y);
            p[1] = make_float4(o[2].x,o[2].y,o[3].x,o[3].y);
        }
    }
}

// ---------------- fused conv1(CIN1)+conv2 full-res: 64x16 out tile ----------
#define E_IW 72
#define E_IH 24
#define E_MW 68
#define E_MH 20
// smem: w(150 ull=1200) + wex(32f=128) + in(72*24*8=13824) + mid(2*68*20*8=21760)
#define ENC12_SMEM (1200 + 128 + E_IW*E_IH*8 + 2*E_MW*E_MH*8)

__global__ void __launch_bounds__(128,6)
k_enc12(const float* __restrict__ xs, const float* __restrict__ cs,
        float2* __restrict__ out, int H, int W, int bpr, int bpc){
    extern __shared__ __align__(16) char dyn[];
    ull*    wpk = (ull*)dyn;                    // [0..150)
    float*  wexs= (float*)(dyn + 1200);         // 32 floats
    float2* inp = (float2*)(dyn + 1328);        // 72x24
    float2* mid = inp + E_IW*E_IH;              // 2 x 68x20

    const int t = threadIdx.x;
    const int P = H*W;
    for(int i=t;i<150;i+=128) wpk[i]=g_wd[i];
    if(t<32) wexs[t]=g_ws[t];

    int bx = blockIdx.x % bpr;
    int tmp = blockIdx.x / bpr;
    int by = tmp % bpc;
    int b  = tmp / bpc;
    const int OX = bx*64, OY = by*16;
    const int fx = t & 31, fy = t >> 5;

    // fill in-plane 72x24 @ (OX-4, OY-4)
    {
        int gx0 = OX-4, gy0 = OY-4;
        const float* cb = cs + (size_t)b*P;
        const float* xb = xs + (size_t)b*P;
        bool inter = gx0>=0 && gy0>=0 && gx0+E_IW<=W && gy0+E_IH<=H;
        if(inter){
            #pragma unroll
            for(int ly=fy; ly<E_IH; ly+=4){
                const float* crow = cb + (size_t)(gy0+ly)*W + gx0;
                const float* xrow = xb + (size_t)(gy0+ly)*W + gx0;
                float2* srow = &inp[ly*E_IW];
                #pragma unroll
                for(int lx=fx; lx<E_IW; lx+=32){
                    float c = crow[lx];
                    srow[lx] = make_float2(c, xrow[lx]*c);
                }
            }
        } else {
            #pragma unroll
            for(int ly=fy; ly<E_IH; ly+=4){
                int gy = gy0+ly;
                float2* srow = &inp[ly*E_IW];
                #pragma unroll
                for(int lx=fx; lx<E_IW; lx+=32){
                    int gx = gx0+lx;
                    float c=0.f,d=0.f;
                    if((unsigned)gx<(unsigned)W && (unsigned)gy<(unsigned)H){
                        int o=gy*W+gx; c=cb[o]; d=xb[o]*c;
                    }
                    srow[lx]=make_float2(c,d);
                }
            }
        }
    }
    __syncthreads();

    // conv1: in(1pl,72) -> mid(2pl,68x20): 17x10=170 tiles
    {
        float rs0=1.0f/wexs[0], rs1=1.0f/wexs[1], bi0=wexs[16], bi1=wexs[17];
        int gx0m = OX-2, gy0m = OY-2;
        for(int idx=t; idx<170; idx+=128){
            int tx4 = (idx % 17)*4, ty2 = (idx / 17)*2;
            ull acc[2][2][4];
            tile5_acc<1>(inp, 0, E_IW, wpk, tx4, ty2, acc);
            epi_mid(acc, mid, E_MW*E_MH, E_MW, tx4, ty2, rs0,rs1,bi0,bi1, gx0m, gy0m, W, H);
        }
        __syncthreads();
    }

    // conv2: mid(2pl,68x20) -> out global, 16x8=128 tiles exact, w@50
    {
        float rs0=1.0f/wexs[2], rs1=1.0f/wexs[3], bi0=wexs[18], bi1=wexs[19];
        int tx4 = (t & 15)*4, ty2 = (t >> 4)*2;
        ull acc[2][2][4];
        tile5_acc<2>(mid, E_MW*E_MH, E_MW, wpk+50, tx4, ty2, acc);

        int gx = OX + tx4;
        int gyp = OY + ty2;
        if(gx < W && gyp < H){
            #pragma unroll
            for(int a=0;a<2;a++){
                float rsa = a ? rs1 : rs0;
                float bia = a ? bi1 : bi0;
                #pragma unroll
                for(int dy=0;dy<2;dy++){
                    float d0,n0,d1,n1,d2,n2,d3,n3;
                    unpack2(acc[a][dy][0], d0, n0);
                    unpack2(acc[a][dy][1], d1, n1);
                    unpack2(acc[a][dy][2], d2, n2);
                    unpack2(acc[a][dy][3], d3, n3);
                    float x0=n0/(d0+EPSV)+bia, c0=d0*rsa;
                    float x1=n1/(d1+EPSV)+bia, c1=d1*rsa;
                    float x2=n2/(d2+EPSV)+bia, c2=d2*rsa;
                    float x3=n3/(d3+EPSV)+bia, c3=d3*rsa;
                    float4* dst = (float4*)(out + (size_t)(b*2+a)*P + (size_t)(gyp+dy)*W + gx);
                    dst[0] = make_float4(c0, x0*c0, c1, x1*c1);
                    dst[1] = make_float4(c2, x2*c2, c3, x3*c3);
                }
            }
        }
    }
}

// ---------------- tiled 5x5 nconv, interleaved I/O, opt. fused pool --------
#define TX5 64
#define TY5 16
#define SW5 (TX5+4)   // 68
#define SH5 (TY5+4)   // 20

template<int CIN, int WOFF, int LYR, bool POOL, bool SPLIT_IN>
__global__ void __launch_bounds__(128,6)
k_nconv5t(const float2* __restrict__ in, const float* __restrict__ xs, const float* __restrict__ cs,
          float2* __restrict__ out, float2* __restrict__ outds,
          int H, int W, int bpr, int bpc){
    __shared__ __align__(16) float2 sm[CIN][SH5*SW5];
    __shared__ __align__(16) ull wpk2[2*CIN*25];
    __shared__ float wex[4];

    const int t = threadIdx.x;
    const int P = H*W;

    for(int i=t;i<2*CIN*25;i+=128) wpk2[i]=g_wd[WOFF+i];
    if(t<2){ wex[t]=g_ws[2*LYR+t]; wex[2+t]=g_ws[16+2*LYR+t]; }

    int bx = blockIdx.x % bpr;
    int tmp = blockIdx.x / bpr;
    int by = tmp % bpc;
    int b  = tmp / bpc;
    int gx0 = bx*TX5 - 2;
    int gy0 = by*TY5 - 2;

    const bool inter = (gx0>=0) && (gy0>=0) && (gx0+SW5<=W) && (gy0+SH5<=H);
    const int fx = t & 31, fy = t >> 5;

    #pragma unroll
    for(int ci=0;ci<CIN;ci++){
        if(!SPLIT_IN){
            const float2* src = in + (size_t)(b*CIN+ci)*P;
            if(inter){
                #pragma unroll
                for(int ly=fy; ly<SH5; ly+=4){
                    const float4* grow = (const float4*)(src + (size_t)(gy0+ly)*W + gx0);
                    float4* srow = (float4*)&sm[ci][ly*SW5];
                    #pragma unroll
                    for(int j=fx; j<SW5/2; j+=32) srow[j] = grow[j];
                }
            } else {
                #pragma unroll
                for(int ly=fy; ly<SH5; ly+=4){
                    int gy = gy0+ly;
                    float2* srow = &sm[ci][ly*SW5];
                    #pragma unroll
                    for(int lx=fx; lx<SW5; lx+=32){
                        int gx = gx0+lx;
                        float2 v = make_float2(0.f, 0.f);
                        if((unsigned)gx<(unsigned)W && (unsigned)gy<(unsigned)H)
                            v = src[(size_t)gy*W+gx];
                        srow[lx] = v;
                    }
                }
            }
        } else {
            const float* cb = cs + (size_t)(b*CIN+ci)*P;
            const float* xb = xs + (size_t)(b*CIN+ci)*P;
            #pragma unroll
            for(int ly=fy; ly<SH5; ly+=4){
                int gy = gy0+ly;
                float2* srow = &sm[ci][ly*SW5];
                #pragma unroll
                for(int lx=fx; lx<SW5; lx+=32){
                    int gx = gx0+lx;
                    float c=0.f, d=0.f;
                    if((unsigned)gx<(unsigned)W && (unsigned)gy<(unsigned)H){
                        int o = gy*W+gx;
                        c = cb[o]; d = xb[o]*c;
                    }
                    srow[lx] = make_float2(c, d);
                }
            }
        }
    }
    __syncthreads();

    const int tx = (t & 15)*4;
    const int ty = (t >> 4)*2;

    ull acc[2][2][4];
    tile5_acc<CIN>(&sm[0][0], SH5*SW5, SW5, wpk2, tx, ty, acc);

    float rs0 = 1.0f/wex[0];
    float rs1 = 1.0f/wex[1];
    int gx = bx*TX5 + tx;
    int gyp = by*TY5 + ty;
    if(gx < W && gyp < H){
        const int Wh = W>>1;
        const int Ph = Wh*(H>>1);
        #pragma unroll
        for(int a=0;a<2;a++){
            float rsa = a ? rs1 : rs0;
            float bia = wex[2+a];
            float rx[2][4], rc[2][4];
            #pragma unroll
            for(int dy=0;dy<2;dy++){
                #pragma unroll
                for(int j=0;j<2;j++){
                    float d0,n0,d1,n1;
                    unpack2(acc[a][dy][2*j],   d0, n0);
                    unpack2(acc[a][dy][2*j+1], d1, n1);
                    rx[dy][2*j]   = n0/(d0+EPSV)+bia;
                    rx[dy][2*j+1] = n1/(d1+EPSV)+bia;
                    rc[dy][2*j]   = d0*rsa;
                    rc[dy][2*j+1] = d1*rsa;
                }
                float4* dst = (float4*)(out + (size_t)(b*2+a)*P + (size_t)(gyp+dy)*W + gx);
                dst[0] = make_float4(rc[dy][0], rx[dy][0]*rc[dy][0],
                                     rc[dy][1], rx[dy][1]*rc[dy][1]);
                dst[1] = make_float4(rc[dy][2], rx[dy][2]*rc[dy][2],
                                     rc[dy][3], rx[dy][3]*rc[dy][3]);
            }
            if(POOL){
                float pc[2], px[2];
                #pragma unroll
                for(int cell=0;cell<2;cell++){
                    int c0 = 2*cell;
                    float bc = rc[0][c0],  bxv = rx[0][c0];
                    if(rc[0][c0+1]>bc){ bc=rc[0][c0+1]; bxv=rx[0][c0+1]; }
                    if(rc[1][c0]  >bc){ bc=rc[1][c0];   bxv=rx[1][c0];   }
                    if(rc[1][c0+1]>bc){ bc=rc[1][c0+1]; bxv=rx[1][c0+1]; }
                    pc[cell] = bc*0.25f;
                    px[cell] = bxv;
                }
                float4* pdst = (float4*)(outds + (size_t)(b*2+a)*Ph + (size_t)(gyp>>1)*Wh + (gx>>1));
                pdst[0] = make_float4(pc[0], px[0]*pc[0], pc[1], px[1]*pc[1]);
            }
        }
    }
}

// ---------------- tiled 3x3 cat nconv, interleaved I/O, opt. fused 1x1 -----
#define TX3 64
#define TY3 16
#define SW3 (TX3+2)   // 66
#define SH3 (TY3+2)   // 18

template<bool UP_FIRST, int WOFF, int LYR, bool FUSE_OUT>
__global__ void __launch_bounds__(128,6)
k_nconv3t(const float2* __restrict__ na, const float2* __restrict__ ub,
          float2* __restrict__ out,
          float* __restrict__ xof, float* __restrict__ cof,
          int H, int W, int bpr, int bpc){
    __shared__ __align__(16) float2 sm[4][SH3*SW3];
    __shared__ __align__(16) ull wpk2[72];
    __shared__ float wex[8];

    const int t = threadIdx.x;
    const int P = H*W;
    const int Wh = W>>1, Ph = (W>>1)*(H>>1);

    for(int i=t;i<72;i+=128) wpk2[i]=g_wd[WOFF+i];
    if(t<2){ wex[t]=g_ws[2*LYR+t]; wex[2+t]=g_ws[16+2*LYR+t]; }
    if(FUSE_OUT && t==0){
        float lo, hi;
        unpack2(g_wd[466], lo, hi); wex[4]=lo;
        unpack2(g_wd[468], lo, hi); wex[5]=lo;
        wex[6]=1.0f/g_ws[12];
        wex[7]=g_ws[28];
    }

    int bx = blockIdx.x % bpr;
    int tmp = blockIdx.x / bpr;
    int by = tmp % bpc;
    int b  = tmp / bpc;
    int gx0 = bx*TX3 - 1;
    int gy0 = by*TY3 - 1;

    const bool inter = (gx0>=0) && (gy0>=0) && (gx0+SW3<=W) && (gy0+SH3<=H);
    const int fx = t & 31, fy = t >> 5;

    #pragma unroll
    for(int ci=0;ci<4;ci++){
        const bool fromUp = UP_FIRST ? (ci<2) : (ci>=2);
        const int ch = fromUp ? (UP_FIRST ? ci : ci-2) : (UP_FIRST ? ci-2 : ci);
        const float2* src = fromUp ? (ub + (size_t)(b*2+ch)*Ph) : (na + (size_t)(b*2+ch)*P);
        if(inter){
            #pragma unroll
            for(int ly=fy; ly<SH3; ly+=4){
                int gy = gy0+ly;
                float2* srow = &sm[ci][ly*SW3];
                if(fromUp){
                    const float2* grow = src + (size_t)(gy>>1)*Wh;
                    #pragma unroll
                    for(int lx=fx; lx<SW3; lx+=32)
                        srow[lx] = grow[(gx0+lx)>>1];
                } else {
                    const float2* grow = src + (size_t)gy*W + gx0;
                    #pragma unroll
                    for(int lx=fx; lx<SW3; lx+=32)
                        srow[lx] = grow[lx];
                }
            }
        } else {
            #pragma unroll
            for(int ly=fy; ly<SH3; ly+=4){
                int gy = gy0+ly;
                float2* srow = &sm[ci][ly*SW3];
                #pragma unroll
                for(int lx=fx; lx<SW3; lx+=32){
                    int gx = gx0+lx;
                    float2 v = make_float2(0.f, 0.f);
                    if((unsigned)gx<(unsigned)W && (unsigned)gy<(unsigned)H)
                        v = fromUp ? src[(size_t)(gy>>1)*Wh + (gx>>1)]
                                   : src[(size_t)gy*W + gx];
                    srow[lx] = v;
                }
            }
        }
    }
    __syncthreads();

    const int tx = (t & 15)*4;
    const int ty = (t >> 4)*2;

    ull acc[2][2][4];
    #pragma unroll
    for(int a=0;a<2;a++)
      #pragma unroll
      for(int dy=0;dy<2;dy++)
        #pragma unroll
        for(int dx=0;dx<4;dx++) acc[a][dy][dx]=0ull;

    #pragma unroll
    for(int ci=0;ci<4;ci++){
        ull v[2][6];
        {
            const longlong2* p = (const longlong2*)&sm[ci][ty*SW3 + tx];
            #pragma unroll
            for(int j=0;j<3;j++){ longlong2 q=p[j]; v[0][2*j]=(ull)q.x; v[0][2*j+1]=(ull)q.y; }
        }
        #pragma unroll
        for(int ky=0;ky<3;ky++){
            const int cur = ky & 1, nxt = (ky+1) & 1;
            {
                const longlong2* p = (const longlong2*)&sm[ci][(ty+ky+1)*SW3 + tx];
                #pragma unroll
                for(int j=0;j<3;j++){ longlong2 q=p[j]; v[nxt][2*j]=(ull)q.x; v[nxt][2*j+1]=(ull)q.y; }
            }
            #pragma unroll
            for(int kx=0;kx<3;kx++){
                longlong2 wp = *(const longlong2*)&wpk2[(ci*9 + ky*3 + kx)*2];
                ull wa=(ull)wp.x, wb=(ull)wp.y;
                #pragma unroll
                for(int dx=0;dx<4;dx++){
                    acc[0][0][dx]=fma2(wa, v[cur][kx+dx], acc[0][0][dx]);
                    acc[1][0][dx]=fma2(wb, v[cur][kx+dx], acc[1][0][dx]);
                    acc[0][1][dx]=fma2(wa, v[nxt][kx+dx], acc[0][1][dx]);
                    acc[1][1][dx]=fma2(wb, v[nxt][kx+dx], acc[1][1][dx]);
                }
            }
        }
    }

    float rs0 = 1.0f/wex[0];
    float rs1 = 1.0f/wex[1];
    float bi0 = wex[2];
    float bi1 = wex[3];
    int gx = bx*TX3 + tx;
    if(gx < W){
        #pragma unroll
        for(int dy=0;dy<2;dy++){
            int gy = by*TY3 + ty + dy;
            if(gy>=H) continue;
            float xc[2][4], cc[2][4];
            #pragma unroll
            for(int a=0;a<2;a++){
                float d0,n0,d1,n1,d2,n2,d3,n3;
                unpack2(acc[a][dy][0], d0, n0);
                unpack2(acc[a][dy][1], d1, n1);
                unpack2(acc[a][dy][2], d2, n2);
                unpack2(acc[a][dy][3], d3, n3);
                float bia = a ? bi1 : bi0;
                float rsa = a ? rs1 : rs0;
                xc[a][0] = n0/(d0+EPSV)+bia; xc[a][1] = n1/(d1+EPSV)+bia;
                xc[a][2] = n2/(d2+EPSV)+bia; xc[a][3] = n3/(d3+EPSV)+bia;
                cc[a][0] = d0*rsa; cc[a][1] = d1*rsa;
                cc[a][2] = d2*rsa; cc[a][3] = d3*rsa;
            }
            if(!FUSE_OUT){
                #pragma unroll
                for(int a=0;a<2;a++){
                    float4* dst = (float4*)(out + (size_t)(b*2+a)*P + (size_t)gy*W + gx);
                    dst[0] = make_float4(cc[a][0], xc[a][0]*cc[a][0],
                                         cc[a][1], xc[a][1]*cc[a][1]);
                    dst[1] = make_float4(cc[a][2], xc[a][2]*cc[a][2],
                                         cc[a][3], xc[a][3]*cc[a][3]);
                }
            } else {
                float w70 = wex[4], w71 = wex[5], rs7 = wex[6], bi7 = wex[7];
                float4 XO, CO;
                #pragma unroll
                for(int k=0;k<4;k++){
                    float den = w70*cc[0][k] + w71*cc[1][k];
                    float nom = w70*xc[0][k]*cc[0][k] + w71*xc[1][k]*cc[1][k];
                    ((float*)&XO)[k] = nom/(den+EPSV) + bi7;
                    ((float*)&CO)[k] = den*rs7;
                }
                size_t o = (size_t)b*P + (size_t)gy*W + gx;
                *(float4*)&xof[o] = XO;
                *(float4*)&cof[o] = CO;
            }
        }
    }
}

extern "C" void kernel_launch(void* const* d_in, const int* in_sizes, int n_in,
                              void* d_out, int out_size){
    const float* x0 = (const float*)d_in[0];
    const float* c0 = (const float*)d_in[1];
    const float* w1 = (const float*)d_in[2];  const float* b1 = (const float*)d_in[3];
    const float* w2 = (const float*)d_in[4];  const float* b2 = (const float*)d_in[5];
    const float* w3 = (const float*)d_in[6];  const float* b3 = (const float*)d_in[7];
    const float* w4 = (const float*)d_in[8];  const float* b4 = (const float*)d_in[9];
    const float* w5 = (const float*)d_in[10]; const float* b5 = (const float*)d_in[11];
    const float* w6 = (const float*)d_in[12]; const float* b6 = (const float*)d_in[13];
    const float* w7 = (const float*)d_in[14]; const float* b7 = (const float*)d_in[15];

    float2* S = nullptr;  cudaGetSymbolAddress((void**)&S,  g_scratch);

    float2 *Bv = S + M0,   *T1 = S + 2*M0;
    float2 *HA = S + 3*M0, *HB = HA + M1,    *T2 = HA + 2*M1;
    float2 *Q  = HA + 3*M1,*T3 = Q + M2,     *T34= Q + 2*M2;
    float2 *E  = Q + 3*M2, *T4 = E + M3;

    auto tiles = [&](int H, int W, int &bpr, int &bpc)->int{
        bpr = (W + TX5 - 1)/TX5; bpc = (H + TY5 - 1)/TY5;
        return bpr*bpc*BB;
    };

    static bool attr_set = false;
    if(!attr_set){
        cudaFuncSetAttribute(k_enc12, cudaFuncAttributeMaxDynamicSharedMemorySize, ENC12_SMEM);
        attr_set = true;
    }

    k_prep<<<1,128>>>(w1,b1,w2,b2,w3,b3,w4,b4,w5,b5,w6,b6,w7,b7);

    int bpr, bpc, g;

    // fused conv1+conv2 full res -> Bv
    g = tiles(H0,W0,bpr,bpc);
    k_enc12<<<g,128,ENC12_SMEM>>>(x0, c0, Bv, H0, W0, bpr, bpc);
    // conv3 + pool -> T1, HA
    k_nconv5t<2,150,2,true,false> <<<g,128>>>(Bv, nullptr, nullptr, T1, HA, H0, W0, bpr, bpc);

    // level 1 (2nd layer fuses pool -> level-2 inputs)
    g = tiles(H1,W1,bpr,bpc);
    k_nconv5t<2,50,1,false,false> <<<g,128>>>(HA, nullptr, nullptr, HB, nullptr, H1, W1, bpr, bpc);
    k_nconv5t<2,150,2,true,false> <<<g,128>>>(HB, nullptr, nullptr, T2, Q, H1, W1, bpr, bpc);

    // level 2 (fuses pool -> level-3 inputs)
    g = tiles(H2,W2,bpr,bpc);
    k_nconv5t<2,50,1,true,false>  <<<g,128>>>(Q, nullptr, nullptr, T3, E, H2, W2, bpr, bpc);

    // level 3
    g = tiles(H3,W3,bpr,bpc);
    k_nconv5t<2,50,1,false,false> <<<g,128>>>(E, nullptr, nullptr, T4, nullptr, H3, W3, bpr, bpc);

    // decoder (last stage fuses the final 1x1 nconv directly into d_out)
    float* out = (float*)d_out;
    bpr = (W2+TX3-1)/TX3; bpc = (H2+TY3-1)/TY3; g = bpr*bpc*BB;
    k_nconv3t<false,250,3,false><<<g,128>>>(T3, T4,  T34, nullptr, nullptr, H2, W2, bpr, bpc);
    bpr = (W1+TX3-1)/TX3; bpc = (H1+TY3-1)/TY3; g = bpr*bpc*BB;
    k_nconv3t<false,322,4,false><<<g,128>>>(T2, T34, HA,  nullptr, nullptr, H1, W1, bpr, bpc);
    bpr = (W0+TX3-1)/TX3; bpc = (H0+TY3-1)/TY3; g = bpr*bpc*BB;
    k_nconv3t<true,394,5,true>  <<<g,128>>>(T1, HA,  nullptr,
                                            out, out + (size_t)BB*P0, H0, W0, bpr, bpc);
}

// round 16
// speedup vs baseline: 1.0029x; 1.0029x over previous
#include <cuda_runtime.h>
#include <math.h>

#define EPSV 1e-20f

#define BB 16
#define H0 352
#define W0 1216
#define H1 176
#define W1 608
#define H2 88
#define W2 304
#define H3 44
#define W3 152

#define P0 (H0*W0)
#define P1 (H1*W1)
#define P2 (H2*W2)
#define P3 (H3*W3)

// float2 element counts per interleaved (c, x*c) tensor
#define M0 ((size_t)BB*2*P0)
#define M1 ((size_t)BB*2*P1)
#define M2 ((size_t)BB*2*P2)
#define M3 ((size_t)BB*2*P3)

typedef unsigned long long ull;

__device__ __align__(16) float2 g_scratch[3*M0 + 3*M1 + 3*M2 + 2*M3];
__device__ ull   g_wd[480];
__device__ float g_ws[32];

// dup-pair weight layout (ull units):
// w1:0(50) w2:50(100) w3:150(100) w4:250(72) w5:322(72) w6:394(72) w7:466(4)
// entry: OFF + (ci*K + k)*2 + cout
// g_ws: sums at [2*lyr + co], biases at [16 + 2*lyr + co]

__device__ __forceinline__ ull fma2(ull a, ull b, ull c){
    ull d; asm("fma.rn.f32x2 %0, %1, %2, %3;" : "=l"(d) : "l"(a), "l"(b), "l"(c)); return d;
}
__device__ __forceinline__ void unpack2(ull v, float &a, float &b){
    asm("mov.b64 {%0,%1}, %2;" : "=f"(a), "=f"(b) : "l"(v));
}
__device__ __forceinline__ ull dupf(float w){
    float2 f2 = make_float2(w, w);
    return *(ull*)&f2;
}
__device__ __forceinline__ float sp10(float p){
    float z = 10.0f * p;
    float r = (z > 20.0f) ? z : log1pf(expf(z));
    return r * 0.1f;
}

__global__ void k_prep(const float* __restrict__ w1, const float* __restrict__ b1,
                       const float* __restrict__ w2, const float* __restrict__ b2,
                       const float* __restrict__ w3, const float* __restrict__ b3,
                       const float* __restrict__ w4, const float* __restrict__ b4,
                       const float* __restrict__ w5, const float* __restrict__ b5,
                       const float* __restrict__ w6, const float* __restrict__ b6,
                       const float* __restrict__ w7, const float* __restrict__ b7){
    const float* wp[7]={w1,w2,w3,w4,w5,w6,w7};
    const float* bp[7]={b1,b2,b3,b4,b5,b6,b7};
    const int cin[7]={1,2,2,4,4,4,2};
    const int kk [7]={25,25,25,9,9,9,1};
    const int co [7]={2,2,2,2,2,2,1};
    const int off[7]={0,50,150,250,322,394,466};
    int t=threadIdx.x;
    for(int l=0;l<7;l++){
        int n=cin[l]*kk[l];
        int tot=n*co[l];
        for(int i=t;i<tot;i+=blockDim.x){
            int c=i/n, e=i%n;
            g_wd[off[l]+e*2+c]=dupf(sp10(wp[l][c*n+e]));
        }
    }
    __syncthreads();
    if(t==0){
        for(int l=0;l<7;l++){
            int n=cin[l]*kk[l];
            for(int c=0;c<co[l];c++){
                float s=0.f;
                for(int e=0;e<n;e++){ float lo,hi; unpack2(g_wd[off[l]+e*2+c],lo,hi); s+=lo; }
                g_ws[2*l+c]=s;
                g_ws[16+2*l+c]=bp[l][c];
            }
        }
    }
}

// ---------------- tiled 5x5 nconv, interleaved I/O, opt. fused pool --------
#define TX5 64
#define TY5 16
#define SW5 (TX5+4)   // 68
#define SH5 (TY5+4)   // 20

template<int CIN, int WOFF, int LYR, bool POOL, bool SPLIT_IN>
__global__ void __launch_bounds__(128,7)
k_nconv5t(const float2* __restrict__ in, const float* __restrict__ xs, const float* __restrict__ cs,
          float2* __restrict__ out, float2* __restrict__ outds,
          int H, int W, int bpr, int bpc){
    __shared__ __align__(16) float2 sm[CIN][SH5*SW5];
    __shared__ __align__(16) ull wpk2[2*CIN*25];
    __shared__ float wex[4];

    const int t = threadIdx.x;
    const int P = H*W;

    for(int i=t;i<2*CIN*25;i+=128) wpk2[i]=g_wd[WOFF+i];
    if(t<2){ wex[t]=g_ws[2*LYR+t]; wex[2+t]=g_ws[16+2*LYR+t]; }

    int bx = blockIdx.x % bpr;
    int tmp = blockIdx.x / bpr;
    int by = tmp % bpc;
    int b  = tmp / bpc;
    int gx0 = bx*TX5 - 2;   // always even
    int gy0 = by*TY5 - 2;

    const bool inter = (gx0>=0) && (gy0>=0) && (gx0+SW5<=W) && (gy0+SH5<=H);
    const int fx = t & 31, fy = t >> 5;

    #pragma unroll
    for(int ci=0;ci<CIN;ci++){
        if(!SPLIT_IN){
            const float2* src = in + (size_t)(b*CIN+ci)*P;
            if(inter){
                #pragma unroll
                for(int ly=fy; ly<SH5; ly+=4){
                    const float4* grow = (const float4*)(src + (size_t)(gy0+ly)*W + gx0);
                    float4* srow = (float4*)&sm[ci][ly*SW5];
                    #pragma unroll
                    for(int j=fx; j<SW5/2; j+=32) srow[j] = grow[j];
                }
            } else {
                #pragma unroll
                for(int ly=fy; ly<SH5; ly+=4){
                    int gy = gy0+ly;
                    float2* srow = &sm[ci][ly*SW5];
                    #pragma unroll
                    for(int lx=fx; lx<SW5; lx+=32){
                        int gx = gx0+lx;
                        float2 v = make_float2(0.f, 0.f);
                        if((unsigned)gx<(unsigned)W && (unsigned)gy<(unsigned)H)
                            v = src[(size_t)gy*W+gx];
                        srow[lx] = v;
                    }
                }
            }
        } else {
            const float* cb = cs + (size_t)(b*CIN+ci)*P;
            const float* xb = xs + (size_t)(b*CIN+ci)*P;
            #pragma unroll
            for(int ly=fy; ly<SH5; ly+=4){
                int gy = gy0+ly;
                float2* srow = &sm[ci][ly*SW5];
                #pragma unroll
                for(int lx=fx; lx<SW5; lx+=32){
                    int gx = gx0+lx;
                    float c=0.f, d=0.f;
                    if((unsigned)gx<(unsigned)W && (unsigned)gy<(unsigned)H){
                        int o = gy*W+gx;
                        c = cb[o]; d = xb[o]*c;
                    }
                    srow[lx] = make_float2(c, d);
                }
            }
        }
    }
    __syncthreads();

    const int tx = (t & 15)*4;
    const int ty = (t >> 4)*2;

    ull acc[2][2][4];
    #pragma unroll
    for(int a=0;a<2;a++)
      #pragma unroll
      for(int dy=0;dy<2;dy++)
        #pragma unroll
        for(int dx=0;dx<4;dx++) acc[a][dy][dx]=0ull;

    // ky-outer, rolling two-row data buffer; each weight pair loaded ONCE.
    #pragma unroll
    for(int ci=0;ci<CIN;ci++){
        ull v[2][8];
        {
            const longlong2* p = (const longlong2*)&sm[ci][ty*SW5 + tx];
            #pragma unroll
            for(int j=0;j<4;j++){ longlong2 q=p[j]; v[0][2*j]=(ull)q.x; v[0][2*j+1]=(ull)q.y; }
        }
        #pragma unroll
        for(int ky=0;ky<5;ky++){
            const int cur = ky & 1, nxt = (ky+1) & 1;
            {
                const longlong2* p = (const longlong2*)&sm[ci][(ty+ky+1)*SW5 + tx];
                #pragma unroll
                for(int j=0;j<4;j++){ longlong2 q=p[j]; v[nxt][2*j]=(ull)q.x; v[nxt][2*j+1]=(ull)q.y; }
            }
            #pragma unroll
            for(int kx=0;kx<5;kx++){
                longlong2 wp = *(const longlong2*)&wpk2[(ci*25 + ky*5 + kx)*2];
                ull wa=(ull)wp.x, wb=(ull)wp.y;
                #pragma unroll
                for(int dx=0;dx<4;dx++){
                    acc[0][0][dx]=fma2(wa, v[cur][kx+dx], acc[0][0][dx]);
                    acc[1][0][dx]=fma2(wb, v[cur][kx+dx], acc[1][0][dx]);
                    acc[0][1][dx]=fma2(wa, v[nxt][kx+dx], acc[0][1][dx]);
                    acc[1][1][dx]=fma2(wb, v[nxt][kx+dx], acc[1][1][dx]);
                }
            }
        }
    }

    float rs0 = 1.0f/wex[0];
    float rs1 = 1.0f/wex[1];
    int gx = bx*TX5 + tx;
    int gyp = by*TY5 + ty;        // even; rows gyp, gyp+1
    if(gx < W && gyp < H){
        const int Wh = W>>1;
        const int Ph = Wh*(H>>1);
        #pragma unroll
        for(int a=0;a<2;a++){
            float rsa = a ? rs1 : rs0;
            float bia = wex[2+a];
            float rx[2][4], rc[2][4];
            #pragma unroll
            for(int dy=0;dy<2;dy++){
                #pragma unroll
                for(int j=0;j<2;j++){
                    float d0,n0,d1,n1;
                    unpack2(acc[a][dy][2*j],   d0, n0);
                    unpack2(acc[a][dy][2*j+1], d1, n1);
                    rx[dy][2*j]   = n0/(d0+EPSV)+bia;
                    rx[dy][2*j+1] = n1/(d1+EPSV)+bia;
                    rc[dy][2*j]   = d0*rsa;
                    rc[dy][2*j+1] = d1*rsa;
                }
                float4* dst = (float4*)(out + (size_t)(b*2+a)*P + (size_t)(gyp+dy)*W + gx);
                dst[0] = make_float4(rc[dy][0], rx[dy][0]*rc[dy][0],
                                     rc[dy][1], rx[dy][1]*rc[dy][1]);
                dst[1] = make_float4(rc[dy][2], rx[dy][2]*rc[dy][2],
                                     rc[dy][3], rx[dy][3]*rc[dy][3]);
            }
            if(POOL){
                float pc[2], px[2];
                #pragma unroll
                for(int cell=0;cell<2;cell++){
                    int c0 = 2*cell;
                    float bc = rc[0][c0],  bxv = rx[0][c0];
                    if(rc[0][c0+1]>bc){ bc=rc[0][c0+1]; bxv=rx[0][c0+1]; }
                    if(rc[1][c0]  >bc){ bc=rc[1][c0];   bxv=rx[1][c0];   }
                    if(rc[1][c0+1]>bc){ bc=rc[1][c0+1]; bxv=rx[1][c0+1]; }
                    pc[cell] = bc*0.25f;
                    px[cell] = bxv;
                }
                float4* pdst = (float4*)(outds + (size_t)(b*2+a)*Ph + (size_t)(gyp>>1)*Wh + (gx>>1));
                pdst[0] = make_float4(pc[0], px[0]*pc[0], pc[1], px[1]*pc[1]);
            }
        }
    }
}

// ---------------- tiled 3x3 cat nconv, interleaved I/O, opt. fused 1x1 -----
#define TX3 64
#define TY3 16
#define SW3 (TX3+2)   // 66
#define SH3 (TY3+2)   // 18

template<bool UP_FIRST, int WOFF, int LYR, bool FUSE_OUT>
__global__ void __launch_bounds__(128,6)
k_nconv3t(const float2* __restrict__ na, const float2* __restrict__ ub,
          float2* __restrict__ out,
          float* __restrict__ xof, float* __restrict__ cof,
          int H, int W, int bpr, int bpc){
    __shared__ __align__(16) float2 sm[4][SH3*SW3];
    __shared__ __align__(16) ull wpk2[72];
    __shared__ float wex[8];

    const int t = threadIdx.x;
    const int P = H*W;
    const int Wh = W>>1, Ph = (W>>1)*(H>>1);

    for(int i=t;i<72;i+=128) wpk2[i]=g_wd[WOFF+i];
    if(t<2){ wex[t]=g_ws[2*LYR+t]; wex[2+t]=g_ws[16+2*LYR+t]; }
    if(FUSE_OUT && t==0){
        float lo, hi;
        unpack2(g_wd[466], lo, hi); wex[4]=lo;       // w7_0
        unpack2(g_wd[468], lo, hi); wex[5]=lo;       // w7_1
        wex[6]=1.0f/g_ws[12];                        // 1/sum7
        wex[7]=g_ws[28];                             // bias7
    }

    int bx = blockIdx.x % bpr;
    int tmp = blockIdx.x / bpr;
    int by = tmp % bpc;
    int b  = tmp / bpc;
    int gx0 = bx*TX3 - 1;
    int gy0 = by*TY3 - 1;

    const bool inter = (gx0>=0) && (gy0>=0) && (gx0+SW3<=W) && (gy0+SH3<=H);
    const int fx = t & 31, fy = t >> 5;

    #pragma unroll
    for(int ci=0;ci<4;ci++){
        const bool fromUp = UP_FIRST ? (ci<2) : (ci>=2);
        const int ch = fromUp ? (UP_FIRST ? ci : ci-2) : (UP_FIRST ? ci-2 : ci);
        const float2* src = fromUp ? (ub + (size_t)(b*2+ch)*Ph) : (na + (size_t)(b*2+ch)*P);
        if(inter){
            #pragma unroll
            for(int ly=fy; ly<SH3; ly+=4){
                int gy = gy0+ly;
                float2* srow = &sm[ci][ly*SW3];
                if(fromUp){
                    const float2* grow = src + (size_t)(gy>>1)*Wh;
                    #pragma unroll
                    for(int lx=fx; lx<SW3; lx+=32)
                        srow[lx] = grow[(gx0+lx)>>1];
                } else {
                    const float2* grow = src + (size_t)gy*W + gx0;
                    #pragma unroll
                    for(int lx=fx; lx<SW3; lx+=32)
                        srow[lx] = grow[lx];
                }
            }
        } else {
            #pragma unroll
            for(int ly=fy; ly<SH3; ly+=4){
                int gy = gy0+ly;
                float2* srow = &sm[ci][ly*SW3];
                #pragma unroll
                for(int lx=fx; lx<SW3; lx+=32){
                    int gx = gx0+lx;
                    float2 v = make_float2(0.f, 0.f);
                    if((unsigned)gx<(unsigned)W && (unsigned)gy<(unsigned)H)
                        v = fromUp ? src[(size_t)(gy>>1)*Wh + (gx>>1)]
                                   : src[(size_t)gy*W + gx];
                    srow[lx] = v;
                }
            }
        }
    }
    __syncthreads();

    const int tx = (t & 15)*4;
    const int ty = (t >> 4)*2;

    ull acc[2][2][4];
    #pragma unroll
    for(int a=0;a<2;a++)
      #pragma unroll
      for(int dy=0;dy<2;dy++)
        #pragma unroll
        for(int dx=0;dx<4;dx++) acc[a][dy][dx]=0ull;

    #pragma unroll
    for(int ci=0;ci<4;ci++){
        ull v[2][6];
        {
            const longlong2* p = (const longlong2*)&sm[ci][ty*SW3 + tx];
            #pragma unroll
            for(int j=0;j<3;j++){ longlong2 q=p[j]; v[0][2*j]=(ull)q.x; v[0][2*j+1]=(ull)q.y; }
        }
        #pragma unroll
        for(int ky=0;ky<3;ky++){
            const int cur = ky & 1, nxt = (ky+1) & 1;
            {
                const longlong2* p = (const longlong2*)&sm[ci][(ty+ky+1)*SW3 + tx];
                #pragma unroll
                for(int j=0;j<3;j++){ longlong2 q=p[j]; v[nxt][2*j]=(ull)q.x; v[nxt][2*j+1]=(ull)q.y; }
            }
            #pragma unroll
            for(int kx=0;kx<3;kx++){
                longlong2 wp = *(const longlong2*)&wpk2[(ci*9 + ky*3 + kx)*2];
                ull wa=(ull)wp.x, wb=(ull)wp.y;
                #pragma unroll
                for(int dx=0;dx<4;dx++){
                    acc[0][0][dx]=fma2(wa, v[cur][kx+dx], acc[0][0][dx]);
                    acc[1][0][dx]=fma2(wb, v[cur][kx+dx], acc[1][0][dx]);
                    acc[0][1][dx]=fma2(wa, v[nxt][kx+dx], acc[0][1][dx]);
                    acc[1][1][dx]=fma2(wb, v[nxt][kx+dx], acc[1][1][dx]);
                }
            }
        }
    }

    float rs0 = 1.0f/wex[0];
    float rs1 = 1.0f/wex[1];
    float bi0 = wex[2];
    float bi1 = wex[3];
    int gx = bx*TX3 + tx;
    if(gx < W){
        #pragma unroll
        for(int dy=0;dy<2;dy++){
            int gy = by*TY3 + ty + dy;
            if(gy>=H) continue;
            float xc[2][4], cc[2][4];
            #pragma unroll
            for(int a=0;a<2;a++){
                float d0,n0,d1,n1,d2,n2,d3,n3;
                unpack2(acc[a][dy][0], d0, n0);
                unpack2(acc[a][dy][1], d1, n1);
                unpack2(acc[a][dy][2], d2, n2);
                unpack2(acc[a][dy][3], d3, n3);
                float bia = a ? bi1 : bi0;
                float rsa = a ? rs1 : rs0;
                xc[a][0] = n0/(d0+EPSV)+bia; xc[a][1] = n1/(d1+EPSV)+bia;
                xc[a][2] = n2/(d2+EPSV)+bia; xc[a][3] = n3/(d3+EPSV)+bia;
                cc[a][0] = d0*rsa; cc[a][1] = d1*rsa;
                cc[a][2] = d2*rsa; cc[a][3] = d3*rsa;
            }
            if(!FUSE_OUT){
                #pragma unroll
                for(int a=0;a<2;a++){
                    float4* dst = (float4*)(out + (size_t)(b*2+a)*P + (size_t)gy*W + gx);
                    dst[0] = make_float4(cc[a][0], xc[a][0]*cc[a][0],
                                         cc[a][1], xc[a][1]*cc[a][1]);
                    dst[1] = make_float4(cc[a][2], xc[a][2]*cc[a][2],
                                         cc[a][3], xc[a][3]*cc[a][3]);
                }
            } else {
                float w70 = wex[4], w71 = wex[5], rs7 = wex[6], bi7 = wex[7];
                float4 XO, CO;
                #pragma unroll
                for(int k=0;k<4;k++){
                    float den = w70*cc[0][k] + w71*cc[1][k];
                    float nom = w70*xc[0][k]*cc[0][k] + w71*xc[1][k]*cc[1][k];
                    ((float*)&XO)[k] = nom/(den+EPSV) + bi7;
                    ((float*)&CO)[k] = den*rs7;
                }
                size_t o = (size_t)b*P + (size_t)gy*W + gx;
                *(float4*)&xof[o] = XO;
                *(float4*)&cof[o] = CO;
            }
        }
    }
}

extern "C" void kernel_launch(void* const* d_in, const int* in_sizes, int n_in,
                              void* d_out, int out_size){
    const float* x0 = (const float*)d_in[0];
    const float* c0 = (const float*)d_in[1];
    const float* w1 = (const float*)d_in[2];  const float* b1 = (const float*)d_in[3];
    const float* w2 = (const float*)d_in[4];  const float* b2 = (const float*)d_in[5];
    const float* w3 = (const float*)d_in[6];  const float* b3 = (const float*)d_in[7];
    const float* w4 = (const float*)d_in[8];  const float* b4 = (const float*)d_in[9];
    const float* w5 = (const float*)d_in[10]; const float* b5 = (const float*)d_in[11];
    const float* w6 = (const float*)d_in[12]; const float* b6 = (const float*)d_in[13];
    const float* w7 = (const float*)d_in[14]; const float* b7 = (const float*)d_in[15];

    float2* S = nullptr;  cudaGetSymbolAddress((void**)&S,  g_scratch);

    float2 *A  = S,        *Bv = S + M0,     *T1 = S + 2*M0;
    float2 *HA = S + 3*M0, *HB = HA + M1,    *T2 = HA + 2*M1;
    float2 *Q  = HA + 3*M1,*T3 = Q + M2,     *T34= Q + 2*M2;
    float2 *E  = Q + 3*M2, *T4 = E + M3;

    auto tiles = [&](int H, int W, int &bpr, int &bpc)->int{
        bpr = (W + TX5 - 1)/TX5; bpc = (H + TY5 - 1)/TY5;
        return bpr*bpc*BB;
    };

    k_prep<<<1,128>>>(w1,b1,w2,b2,w3,b3,w4,b4,w5,b5,w6,b6,w7,b7);

    int bpr, bpc, g;

    // encoder full res (3rd layer fuses pool -> level-1 inputs)
    g = tiles(H0,W0,bpr,bpc);
    k_nconv5t<1,0,0,false,true>   <<<g,128>>>(nullptr, x0, c0, A, nullptr, H0, W0, bpr, bpc);
    k_nconv5t<2,50,1,false,false> <<<g,128>>>(A, nullptr, nullptr, Bv, nullptr, H0, W0, bpr, bpc);
    k_nconv5t<2,150,2,true,false> <<<g,128>>>(Bv, nullptr, nullptr, T1, HA, H0, W0, bpr, bpc);

    // level 1 (2nd layer fuses pool -> level-2 inputs)
    g = tiles(H1,W1,bpr,bpc);
    k_nconv5t<2,50,1,false,false> <<<g,128>>>(HA, nullptr, nullptr, HB, nullptr, H1, W1, bpr, bpc);
    k_nconv5t<2,150,2,true,false> <<<g,128>>>(HB, nullptr, nullptr, T2, Q, H1, W1, bpr, bpc);

    // level 2 (fuses pool -> level-3 inputs)
    g = tiles(H2,W2,bpr,bpc);
    k_nconv5t<2,50,1,true,false>  <<<g,128>>>(Q, nullptr, nullptr, T3, E, H2, W2, bpr, bpc);

    // level 3
    g = tiles(H3,W3,bpr,bpc);
    k_nconv5t<2,50,1,false,false> <<<g,128>>>(E, nullptr, nullptr, T4, nullptr, H3, W3, bpr, bpc);

    // decoder (last stage fuses the final 1x1 nconv directly into d_out)
    float* out = (float*)d_out;
    bpr = (W2+TX3-1)/TX3; bpc = (H2+TY3-1)/TY3; g = bpr*bpc*BB;
    k_nconv3t<false,250,3,false><<<g,128>>>(T3, T4,  T34, nullptr, nullptr, H2, W2, bpr, bpc);
    bpr = (W1+TX3-1)/TX3; bpc = (H1+TY3-1)/TY3; g = bpr*bpc*BB;
    k_nconv3t<false,322,4,false><<<g,128>>>(T2, T34, HA,  nullptr, nullptr, H1, W1, bpr, bpc);
    bpr = (W0+TX3-1)/TX3; bpc = (H0+TY3-1)/TY3; g = bpr*bpc*BB;
    k_nconv3t<true,394,5,true>  <<<g,128>>>(T1, HA,  nullptr,
                                            out, out + (size_t)BB*P0, H0, W0, bpr, bpc);
}

// round 17
// speedup vs baseline: 1.0610x; 1.0580x over previous
#include <cuda_runtime.h>
#include <math.h>

#define EPSV 1e-20f

#define BB 16
#define H0 352
#define W0 1216
#define H1 176
#define W1 608
#define H2 88
#define W2 304
#define H3 44
#define W3 152

#define P0 (H0*W0)
#define P1 (H1*W1)
#define P2 (H2*W2)
#define P3 (H3*W3)

#define M0 ((size_t)BB*2*P0)
#define M1 ((size_t)BB*2*P1)
#define M2 ((size_t)BB*2*P2)
#define M3 ((size_t)BB*2*P3)

typedef unsigned long long ull;

__device__ __align__(16) float2 g_scratch[3*M0 + 3*M1 + 3*M2 + 2*M3];
__device__ ull   g_wd[672];
__device__ float g_ws[32];

// dup-pair weight layout (ull units):
// w1:0(50) w2:50(100) w3:150(100) w4:250(72) w5:322(72) w6:394(72) w7:466(4)
// combined-up decoder weights: l4@480(64) l5@544(64) l6@608(64)
//   entry: UOFF + ((uc*4 + py*2+px)*4 + r*2+c)*2 + a
// g_ws: sums at [2*lyr + co], biases at [16 + 2*lyr + co]

__device__ __forceinline__ ull fma2(ull a, ull b, ull c){
    ull d; asm("fma.rn.f32x2 %0, %1, %2, %3;" : "=l"(d) : "l"(a), "l"(b), "l"(c)); return d;
}
__device__ __forceinline__ void unpack2(ull v, float &a, float &b){
    asm("mov.b64 {%0,%1}, %2;" : "=f"(a), "=f"(b) : "l"(v));
}
__device__ __forceinline__ ull dupf(float w){
    float2 f2 = make_float2(w, w);
    return *(ull*)&f2;
}
__device__ __forceinline__ float sp10(float p){
    float z = 10.0f * p;
    float r = (z > 20.0f) ? z : log1pf(expf(z));
    return r * 0.1f;
}

__global__ void k_prep(const float* __restrict__ w1, const float* __restrict__ b1,
                       const float* __restrict__ w2, const float* __restrict__ b2,
                       const float* __restrict__ w3, const float* __restrict__ b3,
                       const float* __restrict__ w4, const float* __restrict__ b4,
                       const float* __restrict__ w5, const float* __restrict__ b5,
                       const float* __restrict__ w6, const float* __restrict__ b6,
                       const float* __restrict__ w7, const float* __restrict__ b7){
    const float* wp[7]={w1,w2,w3,w4,w5,w6,w7};
    const float* bp[7]={b1,b2,b3,b4,b5,b6,b7};
    const int cin[7]={1,2,2,4,4,4,2};
    const int kk [7]={25,25,25,9,9,9,1};
    const int co [7]={2,2,2,2,2,2,1};
    const int off[7]={0,50,150,250,322,394,466};
    int t=threadIdx.x;
    for(int l=0;l<7;l++){
        int n=cin[l]*kk[l];
        int tot=n*co[l];
        for(int i=t;i<tot;i+=blockDim.x){
            int c=i/n, e=i%n;
            g_wd[off[l]+e*2+c]=dupf(sp10(wp[l][c*n+e]));
        }
    }
    __syncthreads();
    // combined 2x2 phase weights for decoder upsampled channels
    for(int i=t;i<192;i+=blockDim.x){
        int li  = i / 64;
        int rem = i % 64;
        int uc  = rem / 32;
        int a   = (rem % 32) / 16;
        int ph  = (rem % 16) / 4;
        int rc  = rem % 4;
        int py = ph>>1, px = ph&1, r = rc>>1, c = rc&1;
        const int offL[3]={250,322,394};
        const bool upfirst[3]={false,false,true};
        int srcci = upfirst[li] ? uc : uc+2;
        int rows[2], nr, cols[2], nc;
        if(py==0){ if(r==0){rows[0]=0;nr=1;} else {rows[0]=1;rows[1]=2;nr=2;} }
        else     { if(r==0){rows[0]=0;rows[1]=1;nr=2;} else {rows[0]=2;nr=1;} }
        if(px==0){ if(c==0){cols[0]=0;nc=1;} else {cols[0]=1;cols[1]=2;nc=2;} }
        else     { if(c==0){cols[0]=0;cols[1]=1;nc=2;} else {cols[0]=2;nc=1;} }
        float s=0.f;
        for(int ii=0;ii<nr;ii++)
            for(int jj=0;jj<nc;jj++){
                float lo,hi;
                unpack2(g_wd[offL[li] + (srcci*9 + rows[ii]*3 + cols[jj])*2 + a], lo, hi);
                s += lo;
            }
        g_wd[480 + li*64 + ((uc*4 + ph)*4 + rc)*2 + a] = dupf(s);
    }
    if(t==0){
        for(int l=0;l<7;l++){
            int n=cin[l]*kk[l];
            for(int c=0;c<co[l];c++){
                float s=0.f;
                for(int e=0;e<n;e++){ float lo,hi; unpack2(g_wd[off[l]+e*2+c],lo,hi); s+=lo; }
                g_ws[2*l+c]=s;
                g_ws[16+2*l+c]=bp[l][c];
            }
        }
    }
}

// ---------------- tiled 5x5 nconv, interleaved I/O, opt. fused pool --------
#define TX5 64
#define TY5 16
#define SW5 (TX5+4)   // 68
#define SH5 (TY5+4)   // 20

template<int CIN, int WOFF, int LYR, bool POOL, bool SPLIT_IN>
__global__ void __launch_bounds__(128,7)
k_nconv5t(const float2* __restrict__ in, const float* __restrict__ xs, const float* __restrict__ cs,
          float2* __restrict__ out, float2* __restrict__ outds,
          int H, int W, int bpr, int bpc){
    __shared__ __align__(16) float2 sm[CIN][SH5*SW5];
    __shared__ __align__(16) ull wpk2[2*CIN*25];
    __shared__ float wex[4];

    const int t = threadIdx.x;
    const int P = H*W;

    for(int i=t;i<2*CIN*25;i+=128) wpk2[i]=g_wd[WOFF+i];
    if(t<2){ wex[t]=g_ws[2*LYR+t]; wex[2+t]=g_ws[16+2*LYR+t]; }

    int bx = blockIdx.x % bpr;
    int tmp = blockIdx.x / bpr;
    int by = tmp % bpc;
    int b  = tmp / bpc;
    int gx0 = bx*TX5 - 2;
    int gy0 = by*TY5 - 2;

    const bool inter = (gx0>=0) && (gy0>=0) && (gx0+SW5<=W) && (gy0+SH5<=H);
    const int fx = t & 31, fy = t >> 5;

    #pragma unroll
    for(int ci=0;ci<CIN;ci++){
        if(!SPLIT_IN){
            const float2* src = in + (size_t)(b*CIN+ci)*P;
            if(inter){
                #pragma unroll
                for(int ly=fy; ly<SH5; ly+=4){
                    const float4* grow = (const float4*)(src + (size_t)(gy0+ly)*W + gx0);
                    float4* srow = (float4*)&sm[ci][ly*SW5];
                    #pragma unroll
                    for(int j=fx; j<SW5/2; j+=32) srow[j] = grow[j];
                }
            } else {
                #pragma unroll
                for(int ly=fy; ly<SH5; ly+=4){
                    int gy = gy0+ly;
                    float2* srow = &sm[ci][ly*SW5];
                    #pragma unroll
                    for(int lx=fx; lx<SW5; lx+=32){
                        int gx = gx0+lx;
                        float2 v = make_float2(0.f, 0.f);
                        if((unsigned)gx<(unsigned)W && (unsigned)gy<(unsigned)H)
                            v = src[(size_t)gy*W+gx];
                        srow[lx] = v;
                    }
                }
            }
        } else {
            const float* cb = cs + (size_t)(b*CIN+ci)*P;
            const float* xb = xs + (size_t)(b*CIN+ci)*P;
            #pragma unroll
            for(int ly=fy; ly<SH5; ly+=4){
                int gy = gy0+ly;
                float2* srow = &sm[ci][ly*SW5];
                #pragma unroll
                for(int lx=fx; lx<SW5; lx+=32){
                    int gx = gx0+lx;
                    float c=0.f, d=0.f;
                    if((unsigned)gx<(unsigned)W && (unsigned)gy<(unsigned)H){
                        int o = gy*W+gx;
                        c = cb[o]; d = xb[o]*c;
                    }
                    srow[lx] = make_float2(c, d);
                }
            }
        }
    }
    __syncthreads();

    const int tx = (t & 15)*4;
    const int ty = (t >> 4)*2;

    ull acc[2][2][4];
    #pragma unroll
    for(int a=0;a<2;a++)
      #pragma unroll
      for(int dy=0;dy<2;dy++)
        #pragma unroll
        for(int dx=0;dx<4;dx++) acc[a][dy][dx]=0ull;

    #pragma unroll
    for(int ci=0;ci<CIN;ci++){
        ull v[2][8];
        {
            const longlong2* p = (const longlong2*)&sm[ci][ty*SW5 + tx];
            #pragma unroll
            for(int j=0;j<4;j++){ longlong2 q=p[j]; v[0][2*j]=(ull)q.x; v[0][2*j+1]=(ull)q.y; }
        }
        #pragma unroll
        for(int ky=0;ky<5;ky++){
            const int cur = ky & 1, nxt = (ky+1) & 1;
            {
                const longlong2* p = (const longlong2*)&sm[ci][(ty+ky+1)*SW5 + tx];
                #pragma unroll
                for(int j=0;j<4;j++){ longlong2 q=p[j]; v[nxt][2*j]=(ull)q.x; v[nxt][2*j+1]=(ull)q.y; }
            }
            #pragma unroll
            for(int kx=0;kx<5;kx++){
                longlong2 wp = *(const longlong2*)&wpk2[(ci*25 + ky*5 + kx)*2];
                ull wa=(ull)wp.x, wb=(ull)wp.y;
                #pragma unroll
                for(int dx=0;dx<4;dx++){
                    acc[0][0][dx]=fma2(wa, v[cur][kx+dx], acc[0][0][dx]);
                    acc[1][0][dx]=fma2(wb, v[cur][kx+dx], acc[1][0][dx]);
                    acc[0][1][dx]=fma2(wa, v[nxt][kx+dx], acc[0][1][dx]);
                    acc[1][1][dx]=fma2(wb, v[nxt][kx+dx], acc[1][1][dx]);
                }
            }
        }
    }

    float rs0 = 1.0f/wex[0];
    float rs1 = 1.0f/wex[1];
    int gx = bx*TX5 + tx;
    int gyp = by*TY5 + ty;
    if(gx < W && gyp < H){
        const int Wh = W>>1;
        const int Ph = Wh*(H>>1);
        #pragma unroll
        for(int a=0;a<2;a++){
            float rsa = a ? rs1 : rs0;
            float bia = wex[2+a];
            float rx[2][4], rc[2][4];
            #pragma unroll
            for(int dy=0;dy<2;dy++){
                #pragma unroll
                for(int j=0;j<2;j++){
                    float d0,n0,d1,n1;
                    unpack2(acc[a][dy][2*j],   d0, n0);
                    unpack2(acc[a][dy][2*j+1], d1, n1);
                    rx[dy][2*j]   = n0/(d0+EPSV)+bia;
                    rx[dy][2*j+1] = n1/(d1+EPSV)+bia;
                    rc[dy][2*j]   = d0*rsa;
                    rc[dy][2*j+1] = d1*rsa;
                }
                float4* dst = (float4*)(out + (size_t)(b*2+a)*P + (size_t)(gyp+dy)*W + gx);
                dst[0] = make_float4(rc[dy][0], rx[dy][0]*rc[dy][0],
                                     rc[dy][1], rx[dy][1]*rc[dy][1]);
                dst[1] = make_float4(rc[dy][2], rx[dy][2]*rc[dy][2],
                                     rc[dy][3], rx[dy][3]*rc[dy][3]);
            }
            if(POOL){
                float pc[2], px[2];
                #pragma unroll
                for(int cell=0;cell<2;cell++){
                    int c0 = 2*cell;
                    float bc = rc[0][c0],  bxv = rx[0][c0];
                    if(rc[0][c0+1]>bc){ bc=rc[0][c0+1]; bxv=rx[0][c0+1]; }
                    if(rc[1][c0]  >bc){ bc=rc[1][c0];   bxv=rx[1][c0];   }
                    if(rc[1][c0+1]>bc){ bc=rc[1][c0+1]; bxv=rx[1][c0+1]; }
                    pc[cell] = bc*0.25f;
                    px[cell] = bxv;
                }
                float4* pdst = (float4*)(outds + (size_t)(b*2+a)*Ph + (size_t)(gyp>>1)*Wh + (gx>>1));
                pdst[0] = make_float4(pc[0], px[0]*pc[0], pc[1], px[1]*pc[1]);
            }
        }
    }
}

// ---------------- tiled 3x3 cat nconv: native full-res + half-res up -------
// up channels use phase-combined 2x2 weights on half-res data (exact).
#define TX3 64
#define TY3 16
#define SW3 (TX3+2)   // 66
#define SH3 (TY3+2)   // 18
#define UW3 34
#define UH3 10

template<bool UP_FIRST, int WOFF, int UOFF, int LYR, bool FUSE_OUT>
__global__ void __launch_bounds__(128,6)
k_nconv3t(const float2* __restrict__ na, const float2* __restrict__ ub,
          float2* __restrict__ out,
          float* __restrict__ xof, float* __restrict__ cof,
          int H, int W, int bpr, int bpc){
    __shared__ __align__(16) float2 smn[2][SH3*SW3];
    __shared__ __align__(16) float2 smu[2][UH3*UW3];
    __shared__ __align__(16) ull wnat[36];
    __shared__ __align__(16) ull wup[64];
    __shared__ float wex[8];

    const int t = threadIdx.x;
    const int P = H*W;
    const int Wh = W>>1, Hh = H>>1;
    const int Ph = Wh*Hh;

    // native weights remapped to planes 0,1
    for(int i=t;i<36;i+=128){
        int cn = i/18, k = (i%18)>>1, a = i&1;
        int src = UP_FIRST ? cn+2 : cn;
        wnat[i] = g_wd[WOFF + (src*9+k)*2 + a];
    }
    for(int i=t;i<64;i+=128) wup[i] = g_wd[UOFF+i];
    if(t<2){ wex[t]=g_ws[2*LYR+t]; wex[2+t]=g_ws[16+2*LYR+t]; }
    if(FUSE_OUT && t==0){
        float lo, hi;
        unpack2(g_wd[466], lo, hi); wex[4]=lo;
        unpack2(g_wd[468], lo, hi); wex[5]=lo;
        wex[6]=1.0f/g_ws[12];
        wex[7]=g_ws[28];
    }

    int bx = blockIdx.x % bpr;
    int tmp = blockIdx.x / bpr;
    int by = tmp % bpc;
    int b  = tmp / bpc;
    const int OX = bx*TX3, OY = by*TY3;
    int gx0 = OX - 1;
    int gy0 = OY - 1;

    const bool inter = (gx0>=0) && (gy0>=0) && (gx0+SW3<=W) && (gy0+SH3<=H);
    const int fx = t & 31, fy = t >> 5;

    // fill native full-res planes
    #pragma unroll
    for(int cn=0;cn<2;cn++){
        const float2* src = na + (size_t)(b*2+cn)*P;
        if(inter){
            #pragma unroll
            for(int ly=fy; ly<SH3; ly+=4){
                const float2* grow = src + (size_t)(gy0+ly)*W + gx0;
                float2* srow = &smn[cn][ly*SW3];
                #pragma unroll
                for(int lx=fx; lx<SW3; lx+=32) srow[lx] = grow[lx];
            }
        } else {
            #pragma unroll
            for(int ly=fy; ly<SH3; ly+=4){
                int gy = gy0+ly;
                float2* srow = &smn[cn][ly*SW3];
                #pragma unroll
                for(int lx=fx; lx<SW3; lx+=32){
                    int gx = gx0+lx;
                    float2 v = make_float2(0.f, 0.f);
                    if((unsigned)gx<(unsigned)W && (unsigned)gy<(unsigned)H)
                        v = src[(size_t)gy*W + gx];
                    srow[lx] = v;
                }
            }
        }
    }
    // fill half-res up planes (10 x 34) @ (OXh-1, OYh-1)
    {
        const int hx0 = (OX>>1)-1, hy0 = (OY>>1)-1;
        #pragma unroll
        for(int uc=0;uc<2;uc++){
            const float2* src = ub + (size_t)(b*2+uc)*Ph;
            for(int i=t;i<UH3*UW3;i+=128){
                int lc = i % UW3, lr = i / UW3;
                int hy = hy0+lr, hx = hx0+lc;
                float2 v = make_float2(0.f,0.f);
                if((unsigned)hx<(unsigned)Wh && (unsigned)hy<(unsigned)Hh)
                    v = src[(size_t)hy*Wh + hx];
                smu[uc][i] = v;
            }
        }
    }
    __syncthreads();

    const int tx = (t & 15)*4;
    const int ty = (t >> 4)*2;

    ull acc[2][2][4];
    #pragma unroll
    for(int a=0;a<2;a++)
      #pragma unroll
      for(int dy=0;dy<2;dy++)
        #pragma unroll
        for(int dx=0;dx<4;dx++) acc[a][dy][dx]=0ull;

    // native channels: rolling 3x3
    #pragma unroll
    for(int cn=0;cn<2;cn++){
        ull v[2][6];
        {
            const longlong2* p = (const longlong2*)&smn[cn][ty*SW3 + tx];
            #pragma unroll
            for(int j=0;j<3;j++){ longlong2 q=p[j]; v[0][2*j]=(ull)q.x; v[0][2*j+1]=(ull)q.y; }
        }
        #pragma unroll
        for(int ky=0;ky<3;ky++){
            const int cur = ky & 1, nxt = (ky+1) & 1;
            {
                const longlong2* p = (const longlong2*)&smn[cn][(ty+ky+1)*SW3 + tx];
                #pragma unroll
                for(int j=0;j<3;j++){ longlong2 q=p[j]; v[nxt][2*j]=(ull)q.x; v[nxt][2*j+1]=(ull)q.y; }
            }
            #pragma unroll
            for(int kx=0;kx<3;kx++){
                longlong2 wp = *(const longlong2*)&wnat[(cn*9 + ky*3 + kx)*2];
                ull wa=(ull)wp.x, wb=(ull)wp.y;
                #pragma unroll
                for(int dx=0;dx<4;dx++){
                    acc[0][0][dx]=fma2(wa, v[cur][kx+dx], acc[0][0][dx]);
                    acc[1][0][dx]=fma2(wb, v[cur][kx+dx], acc[1][0][dx]);
                    acc[0][1][dx]=fma2(wa, v[nxt][kx+dx], acc[0][1][dx]);
                    acc[1][1][dx]=fma2(wb, v[nxt][kx+dx], acc[1][1][dx]);
                }
            }
        }
    }

    // up channels: 2x2 phase-combined on half-res
    {
        const int lr0 = ty>>1;   // local row base (maps to global m-1)
        const int lc0 = tx>>1;   // local col base (maps to global nb-1)
        #pragma unroll
        for(int uc=0;uc<2;uc++){
            ull u[3][4];
            #pragma unroll
            for(int r=0;r<3;r++){
                const float2* p = &smu[uc][(lr0+r)*UW3 + lc0];
                #pragma unroll
                for(int c=0;c<4;c++){ float2 q=p[c]; u[r][c]=*(ull*)&q; }
            }
            #pragma unroll
            for(int py=0;py<2;py++){
                #pragma unroll
                for(int px=0;px<2;px++){
                    ull K0a,K0b,K1a,K1b,K2a,K2b,K3a,K3b;
                    {
                        const longlong2* wp = (const longlong2*)&wup[((uc*4+py*2+px)*4)*2];
                        longlong2 q0=wp[0], q1=wp[1], q2=wp[2], q3=wp[3];
                        K0a=(ull)q0.x; K0b=(ull)q0.y;
                        K1a=(ull)q1.x; K1b=(ull)q1.y;
                        K2a=(ull)q2.x; K2b=(ull)q2.y;
                        K3a=(ull)q3.x; K3b=(ull)q3.y;
                    }
                    #pragma unroll
                    for(int dxh=0;dxh<2;dxh++){
                        int dx = dxh*2+px;
                        int coff = dxh+px;
                        acc[0][py][dx]=fma2(K0a, u[py][coff],     acc[0][py][dx]);
                        acc[0][py][dx]=fma2(K1a, u[py][coff+1],   acc[0][py][dx]);
                        acc[0][py][dx]=fma2(K2a, u[py+1][coff],   acc[0][py][dx]);
                        acc[0][py][dx]=fma2(K3a, u[py+1][coff+1], acc[0][py][dx]);
                        acc[1][py][dx]=fma2(K0b, u[py][coff],     acc[1][py][dx]);
                        acc[1][py][dx]=fma2(K1b, u[py][coff+1],   acc[1][py][dx]);
                        acc[1][py][dx]=fma2(K2b, u[py+1][coff],   acc[1][py][dx]);
                        acc[1][py][dx]=fma2(K3b, u[py+1][coff+1], acc[1][py][dx]);
                    }
                }
            }
        }
    }

    float rs0 = 1.0f/wex[0];
    float rs1 = 1.0f/wex[1];
    float bi0 = wex[2];
    float bi1 = wex[3];
    int gx = OX + tx;
    if(gx < W){
        #pragma unroll
        for(int dy=0;dy<2;dy++){
            int gy = OY + ty + dy;
            if(gy>=H) continue;
            float xc[2][4], cc[2][4];
            #pragma unroll
            for(int a=0;a<2;a++){
                float d0,n0,d1,n1,d2,n2,d3,n3;
                unpack2(acc[a][dy][0], d0, n0);
                unpack2(acc[a][dy][1], d1, n1);
                unpack2(acc[a][dy][2], d2, n2);
                unpack2(acc[a][dy][3], d3, n3);
                float bia = a ? bi1 : bi0;
                float rsa = a ? rs1 : rs0;
                xc[a][0] = n0/(d0+EPSV)+bia; xc[a][1] = n1/(d1+EPSV)+bia;
                xc[a][2] = n2/(d2+EPSV)+bia; xc[a][3] = n3/(d3+EPSV)+bia;
                cc[a][0] = d0*rsa; cc[a][1] = d1*rsa;
                cc[a][2] = d2*rsa; cc[a][3] = d3*rsa;
            }
            if(!FUSE_OUT){
                #pragma unroll
                for(int a=0;a<2;a++){
                    float4* dst = (float4*)(out + (size_t)(b*2+a)*P + (size_t)gy*W + gx);
                    dst[0] = make_float4(cc[a][0], xc[a][0]*cc[a][0],
                                         cc[a][1], xc[a][1]*cc[a][1]);
                    dst[1] = make_float4(cc[a][2], xc[a][2]*cc[a][2],
                                         cc[a][3], xc[a][3]*cc[a][3]);
                }
            } else {
                float w70 = wex[4], w71 = wex[5], rs7 = wex[6], bi7 = wex[7];
                float4 XO, CO;
                #pragma unroll
                for(int k=0;k<4;k++){
                    float den = w70*cc[0][k] + w71*cc[1][k];
                    float nom = w70*xc[0][k]*cc[0][k] + w71*xc[1][k]*cc[1][k];
                    ((float*)&XO)[k] = nom/(den+EPSV) + bi7;
                    ((float*)&CO)[k] = den*rs7;
                }
                size_t o = (size_t)b*P + (size_t)gy*W + gx;
                *(float4*)&xof[o] = XO;
                *(float4*)&cof[o] = CO;
            }
        }
    }
}

extern "C" void kernel_launch(void* const* d_in, const int* in_sizes, int n_in,
                              void* d_out, int out_size){
    const float* x0 = (const float*)d_in[0];
    const float* c0 = (const float*)d_in[1];
    const float* w1 = (const float*)d_in[2];  const float* b1 = (const float*)d_in[3];
    const float* w2 = (const float*)d_in[4];  const float* b2 = (const float*)d_in[5];
    const float* w3 = (const float*)d_in[6];  const float* b3 = (const float*)d_in[7];
    const float* w4 = (const float*)d_in[8];  const float* b4 = (const float*)d_in[9];
    const float* w5 = (const float*)d_in[10]; const float* b5 = (const float*)d_in[11];
    const float* w6 = (const float*)d_in[12]; const float* b6 = (const float*)d_in[13];
    const float* w7 = (const float*)d_in[14]; const float* b7 = (const float*)d_in[15];

    float2* S = nullptr;  cudaGetSymbolAddress((void**)&S,  g_scratch);

    float2 *A  = S,        *Bv = S + M0,     *T1 = S + 2*M0;
    float2 *HA = S + 3*M0, *HB = HA + M1,    *T2 = HA + 2*M1;
    float2 *Q  = HA + 3*M1,*T3 = Q + M2,     *T34= Q + 2*M2;
    float2 *E  = Q + 3*M2, *T4 = E + M3;

    auto tiles = [&](int H, int W, int &bpr, int &bpc)->int{
        bpr = (W + TX5 - 1)/TX5; bpc = (H + TY5 - 1)/TY5;
        return bpr*bpc*BB;
    };

    k_prep<<<1,192>>>(w1,b1,w2,b2,w3,b3,w4,b4,w5,b5,w6,b6,w7,b7);

    int bpr, bpc, g;

    // encoder full res (3rd layer fuses pool -> level-1 inputs)
    g = tiles(H0,W0,bpr,bpc);
    k_nconv5t<1,0,0,false,true>   <<<g,128>>>(nullptr, x0, c0, A, nullptr, H0, W0, bpr, bpc);
    k_nconv5t<2,50,1,false,false> <<<g,128>>>(A, nullptr, nullptr, Bv, nullptr, H0, W0, bpr, bpc);
    k_nconv5t<2,150,2,true,false> <<<g,128>>>(Bv, nullptr, nullptr, T1, HA, H0, W0, bpr, bpc);

    // level 1 (2nd layer fuses pool -> level-2 inputs)
    g = tiles(H1,W1,bpr,bpc);
    k_nconv5t<2,50,1,false,false> <<<g,128>>>(HA, nullptr, nullptr, HB, nullptr, H1, W1, bpr, bpc);
    k_nconv5t<2,150,2,true,false> <<<g,128>>>(HB, nullptr, nullptr, T2, Q, H1, W1, bpr, bpc);

    // level 2 (fuses pool -> level-3 inputs)
    g = tiles(H2,W2,bpr,bpc);
    k_nconv5t<2,50,1,true,false>  <<<g,128>>>(Q, nullptr, nullptr, T3, E, H2, W2, bpr, bpc);

    // level 3
    g = tiles(H3,W3,bpr,bpc);
    k_nconv5t<2,50,1,false,false> <<<g,128>>>(E, nullptr, nullptr, T4, nullptr, H3, W3, bpr, bpc);

    // decoder (half-res up channels with phase-combined weights)
    float* out = (float*)d_out;
    bpr = (W2+TX3-1)/TX3; bpc = (H2+TY3-1)/TY3; g = bpr*bpc*BB;
    k_nconv3t<false,250,480,3,false><<<g,128>>>(T3, T4,  T34, nullptr, nullptr, H2, W2, bpr, bpc);
    bpr = (W1+TX3-1)/TX3; bpc = (H1+TY3-1)/TY3; g = bpr*bpc*BB;
    k_nconv3t<false,322,544,4,false><<<g,128>>>(T2, T34, HA,  nullptr, nullptr, H1, W1, bpr, bpc);
    bpr = (W0+TX3-1)/TX3; bpc = (H0+TY3-1)/TY3; g = bpr*bpc*BB;
    k_nconv3t<true,394,608,5,true>  <<<g,128>>>(T1, HA,  nullptr,
                                                out, out + (size_t)BB*P0, H0, W0, bpr, bpc);
}